// round 1
// baseline (speedup 1.0000x reference)
#include <cuda_runtime.h>
#include <math.h>

#define N_NODES 50000
#define N_EDGES 400000
#define IN_F    512
#define HID     512
#define OUT_F   256
#define N_SEL   8192
#define N_C     1024
#define N_DIM   128
#define N_CELL  1000

// ---------------- scratch (device globals; no runtime allocation) ----------
__device__ float g_bufA[(size_t)N_NODES * HID];   // 102.4 MB
__device__ float g_bufB[(size_t)N_NODES * HID];   // 102.4 MB
__device__ float g_ns[N_NODES];
__device__ float g_nd[N_NODES];
__device__ int   g_deg_out[N_NODES];
__device__ int   g_deg_in[N_NODES];
__device__ int   g_rowptr[N_NODES + 1];
__device__ int   g_cursor[N_NODES];
__device__ int   g_esrc[N_EDGES];
__device__ float g_proj[(size_t)N_SEL * N_DIM];   // 4 MB

// ---------------- graph preprocessing --------------------------------------
__global__ void zero_deg_kernel() {
    int i = blockIdx.x * blockDim.x + threadIdx.x;
    for (; i < N_NODES; i += gridDim.x * blockDim.x) {
        g_deg_out[i] = 0;
        g_deg_in[i]  = 0;
    }
}

__global__ void hist_kernel(const int* __restrict__ src, const int* __restrict__ dst) {
    int i = blockIdx.x * blockDim.x + threadIdx.x;
    for (; i < N_EDGES; i += gridDim.x * blockDim.x) {
        atomicAdd(&g_deg_out[src[i]], 1);
        atomicAdd(&g_deg_in[dst[i]], 1);
    }
}

__global__ void norm_kernel() {
    int i = blockIdx.x * blockDim.x + threadIdx.x;
    for (; i < N_NODES; i += gridDim.x * blockDim.x) {
        int dout = g_deg_out[i];
        int din  = g_deg_in[i];
        g_ns[i] = dout > 0 ? rsqrtf((float)dout) : 0.0f;
        g_nd[i] = din  > 0 ? rsqrtf((float)din)  : 0.0f;
    }
}

// single-block exclusive scan of deg_in -> rowptr (and cursor)
__global__ void scan_kernel() {
    __shared__ int sh[1024];
    int tid = threadIdx.x;
    int base = 0;
    for (int c0 = 0; c0 < N_NODES; c0 += 1024) {
        int i = c0 + tid;
        int v = (i < N_NODES) ? g_deg_in[i] : 0;
        sh[tid] = v;
        __syncthreads();
        #pragma unroll
        for (int off = 1; off < 1024; off <<= 1) {
            int t = (tid >= off) ? sh[tid - off] : 0;
            __syncthreads();
            sh[tid] += t;
            __syncthreads();
        }
        int incl = sh[tid];
        int tot  = sh[1023];
        if (i < N_NODES) {
            int excl = base + incl - v;
            g_rowptr[i] = excl;
            g_cursor[i] = excl;
        }
        base += tot;
        __syncthreads();
    }
    if (tid == 0) g_rowptr[N_NODES] = base;
}

__global__ void fill_kernel(const int* __restrict__ src, const int* __restrict__ dst) {
    int i = blockIdx.x * blockDim.x + threadIdx.x;
    for (; i < N_EDGES; i += gridDim.x * blockDim.x) {
        int p = atomicAdd(&g_cursor[dst[i]], 1);
        g_esrc[p] = src[i];
    }
}

// ---------------- SGEMM: C[M,N] = A[M,K] @ B[K,N]  (128x128x8, 8x8/thread) --
__global__ __launch_bounds__(256)
void sgemm_kernel(const float* __restrict__ A, const float* __restrict__ B,
                  float* __restrict__ C, int M, int N, int K) {
    __shared__ float As[8][128];
    __shared__ float Bs[8][128];

    int tid  = threadIdx.x;
    int row0 = blockIdx.y * 128;
    int col0 = blockIdx.x * 128;
    int tx = tid & 15;        // 0..15
    int ty = tid >> 4;        // 0..15

    int arow = tid >> 1;          // 0..127
    int acol = (tid & 1) * 4;     // 0 or 4
    int brow = tid >> 5;          // 0..7
    int bcol = (tid & 31) * 4;    // 0..124

    float acc[8][8];
    #pragma unroll
    for (int i = 0; i < 8; i++)
        #pragma unroll
        for (int j = 0; j < 8; j++) acc[i][j] = 0.0f;

    for (int k0 = 0; k0 < K; k0 += 8) {
        float4 av;
        if (row0 + arow < M)
            av = *(const float4*)&A[(size_t)(row0 + arow) * K + k0 + acol];
        else
            av = make_float4(0.f, 0.f, 0.f, 0.f);
        As[acol + 0][arow] = av.x;
        As[acol + 1][arow] = av.y;
        As[acol + 2][arow] = av.z;
        As[acol + 3][arow] = av.w;

        float4 bv = *(const float4*)&B[(size_t)(k0 + brow) * N + col0 + bcol];
        *(float4*)&Bs[brow][bcol] = bv;

        __syncthreads();
        #pragma unroll
        for (int kk = 0; kk < 8; kk++) {
            float a[8], b[8];
            #pragma unroll
            for (int i = 0; i < 8; i++) a[i] = As[kk][ty * 8 + i];
            #pragma unroll
            for (int j = 0; j < 8; j++) b[j] = Bs[kk][tx * 8 + j];
            #pragma unroll
            for (int i = 0; i < 8; i++)
                #pragma unroll
                for (int j = 0; j < 8; j++) acc[i][j] = fmaf(a[i], b[j], acc[i][j]);
        }
        __syncthreads();
    }

    #pragma unroll
    for (int i = 0; i < 8; i++) {
        int r = row0 + ty * 8 + i;
        if (r < M) {
            float4 v0 = make_float4(acc[i][0], acc[i][1], acc[i][2], acc[i][3]);
            float4 v1 = make_float4(acc[i][4], acc[i][5], acc[i][6], acc[i][7]);
            *(float4*)&C[(size_t)r * N + col0 + tx * 8]     = v0;
            *(float4*)&C[(size_t)r * N + col0 + tx * 8 + 4] = v1;
        }
    }
}

// ---------------- CSR aggregation: out[d] = relu(nd[d]*sum_e ns[s]*Z[s] + b) -
__global__ void agg_kernel(const float* __restrict__ Z, float* __restrict__ out,
                           const float* __restrict__ bias, int F) {
    int d = blockIdx.x;
    int t = threadIdx.x;          // blockDim = F/4
    int nvec = F >> 2;

    float4 acc = make_float4(0.f, 0.f, 0.f, 0.f);
    int beg = g_rowptr[d];
    int end = g_rowptr[d + 1];
    const float4* Z4 = (const float4*)Z;
    for (int e = beg; e < end; ++e) {
        int s = g_esrc[e];
        float w = g_ns[s];
        float4 z = Z4[(size_t)s * nvec + t];
        acc.x = fmaf(w, z.x, acc.x);
        acc.y = fmaf(w, z.y, acc.y);
        acc.z = fmaf(w, z.z, acc.z);
        acc.w = fmaf(w, z.w, acc.w);
    }
    float ndv = g_nd[d];
    float4 b = ((const float4*)bias)[t];
    float4 r;
    r.x = fmaxf(fmaf(ndv, acc.x, b.x), 0.f);
    r.y = fmaxf(fmaf(ndv, acc.y, b.y), 0.f);
    r.z = fmaxf(fmaf(ndv, acc.z, b.z), 0.f);
    r.w = fmaxf(fmaf(ndv, acc.w, b.w), 0.f);
    ((float4*)out)[(size_t)d * nvec + t] = r;
}

// ---------------- proj = h3[x_indices] @ Wp + bp  (M=8192, K=256, N=128) ----
__global__ __launch_bounds__(128)
void proj_kernel(const float* __restrict__ H, const int* __restrict__ xidx,
                 const float* __restrict__ Wp, const float* __restrict__ bp,
                 float* __restrict__ P) {
    __shared__ float enc[OUT_F];
    int m = blockIdx.x;
    int t = threadIdx.x;   // 128
    int row = xidx[m];
    enc[t]       = H[(size_t)row * OUT_F + t];
    enc[t + 128] = H[(size_t)row * OUT_F + t + 128];
    __syncthreads();
    float a0 = 0.f, a1 = 0.f, a2 = 0.f, a3 = 0.f;
    #pragma unroll 4
    for (int k = 0; k < OUT_F; k += 4) {
        a0 = fmaf(enc[k + 0], Wp[(size_t)(k + 0) * N_DIM + t], a0);
        a1 = fmaf(enc[k + 1], Wp[(size_t)(k + 1) * N_DIM + t], a1);
        a2 = fmaf(enc[k + 2], Wp[(size_t)(k + 2) * N_DIM + t], a2);
        a3 = fmaf(enc[k + 3], Wp[(size_t)(k + 3) * N_DIM + t], a3);
    }
    P[(size_t)m * N_DIM + t] = bp[t] + (a0 + a1) + (a2 + a3);
}

// ---------------- out[c][s] = dot(emb[c_indices[c]], proj[s])  (K=128) ------
__global__ __launch_bounds__(256)
void out_gemm_kernel(const float* __restrict__ emb, const int* __restrict__ cidx,
                     const float* __restrict__ P, float* __restrict__ out) {
    __shared__ float Es[64][33];
    __shared__ float Ps[64][33];
    int s0 = blockIdx.x * 64;
    int c0 = blockIdx.y * 64;
    int tid = threadIdx.x;
    int tx = tid & 15, ty = tid >> 4;

    float acc[4][4];
    #pragma unroll
    for (int i = 0; i < 4; i++)
        #pragma unroll
        for (int j = 0; j < 4; j++) acc[i][j] = 0.f;

    for (int k0 = 0; k0 < N_DIM; k0 += 32) {
        #pragma unroll
        for (int i = 0; i < 2; i++) {
            int idx = tid * 2 + i;          // 0..511
            int r = idx >> 3;               // 0..63
            int c = (idx & 7) * 4;          // 0..28
            int erow = cidx[c0 + r];
            float4 v = *(const float4*)&emb[(size_t)erow * N_DIM + k0 + c];
            Es[r][c] = v.x; Es[r][c + 1] = v.y; Es[r][c + 2] = v.z; Es[r][c + 3] = v.w;
            float4 p = *(const float4*)&P[(size_t)(s0 + r) * N_DIM + k0 + c];
            Ps[r][c] = p.x; Ps[r][c + 1] = p.y; Ps[r][c + 2] = p.z; Ps[r][c + 3] = p.w;
        }
        __syncthreads();
        #pragma unroll
        for (int kk = 0; kk < 32; kk++) {
            float a[4], b[4];
            #pragma unroll
            for (int i = 0; i < 4; i++) a[i] = Es[ty * 4 + i][kk];
            #pragma unroll
            for (int j = 0; j < 4; j++) b[j] = Ps[tx * 4 + j][kk];
            #pragma unroll
            for (int i = 0; i < 4; i++)
                #pragma unroll
                for (int j = 0; j < 4; j++) acc[i][j] = fmaf(a[i], b[j], acc[i][j]);
        }
        __syncthreads();
    }
    #pragma unroll
    for (int i = 0; i < 4; i++) {
        float4 v = make_float4(acc[i][0], acc[i][1], acc[i][2], acc[i][3]);
        *(float4*)&out[(size_t)(c0 + ty * 4 + i) * N_SEL + s0 + tx * 4] = v;
    }
}

// ---------------- launch ----------------------------------------------------
extern "C" void kernel_launch(void* const* d_in, const int* in_sizes, int n_in,
                              void* d_out, int out_size) {
    const float* x    = (const float*)d_in[0];
    const int*   src  = (const int*)d_in[1];
    const int*   dst  = (const int*)d_in[2];
    const int*   xidx = (const int*)d_in[3];
    const int*   cidx = (const int*)d_in[4];
    const float* W1   = (const float*)d_in[5];
    const float* b1   = (const float*)d_in[6];
    const float* W2   = (const float*)d_in[7];
    const float* b2   = (const float*)d_in[8];
    const float* W3   = (const float*)d_in[9];
    const float* b3   = (const float*)d_in[10];
    const float* Wp   = (const float*)d_in[11];
    const float* bp   = (const float*)d_in[12];
    const float* emb  = (const float*)d_in[13];
    float* out = (float*)d_out;

    float *bufA, *bufB, *proj;
    cudaGetSymbolAddress((void**)&bufA, g_bufA);
    cudaGetSymbolAddress((void**)&bufB, g_bufB);
    cudaGetSymbolAddress((void**)&proj, g_proj);

    // graph preprocessing (per launch; deterministic work)
    zero_deg_kernel<<<196, 256>>>();
    hist_kernel<<<512, 256>>>(src, dst);
    norm_kernel<<<196, 256>>>();
    scan_kernel<<<1, 1024>>>();
    fill_kernel<<<512, 256>>>(src, dst);

    const int MB = (N_NODES + 127) / 128;   // 391

    // Layer 1: Z = x @ W1 ; h1 = relu(nd * agg(ns*Z) + b1)
    sgemm_kernel<<<dim3(HID / 128, MB), 256>>>(x, W1, bufA, N_NODES, HID, IN_F);
    agg_kernel<<<N_NODES, HID / 4>>>(bufA, bufB, b1, HID);

    // Layer 2
    sgemm_kernel<<<dim3(HID / 128, MB), 256>>>(bufB, W2, bufA, N_NODES, HID, HID);
    agg_kernel<<<N_NODES, HID / 4>>>(bufA, bufB, b2, HID);

    // Layer 3 (output width 256)
    sgemm_kernel<<<dim3(OUT_F / 128, MB), 256>>>(bufB, W3, bufA, N_NODES, OUT_F, HID);
    agg_kernel<<<N_NODES, OUT_F / 4>>>(bufA, bufB, b3, OUT_F);

    // proj = h3[x_indices] @ Wp + bp
    proj_kernel<<<N_SEL, 128>>>(bufB, xidx, Wp, bp, proj);

    // out = emb[c_indices] @ proj.T
    out_gemm_kernel<<<dim3(N_SEL / 64, N_C / 64), 256>>>(emb, cidx, proj, out);
}

// round 3
// speedup vs baseline: 1.9675x; 1.9675x over previous
#include <cuda_runtime.h>
#include <cuda_bf16.h>
#include <math.h>
#include <stdint.h>

#define N_NODES 50000
#define N_EDGES 400000
#define IN_F    512
#define HID     512
#define OUT_F   256
#define N_SEL   8192
#define N_C     1024
#define N_DIM   128
#define GK      512        // K of all three big GEMMs

// ---------------- scratch (device globals) ----------------------------------
__device__ float          g_Z  [(size_t)N_NODES * HID];     // GEMM output (pre-agg)
__device__ float          g_h3 [(size_t)N_NODES * OUT_F];   // layer-3 activations
__device__ __nv_bfloat16  g_Ahi[(size_t)N_NODES * HID];
__device__ __nv_bfloat16  g_Alo[(size_t)N_NODES * HID];
__device__ __nv_bfloat16  g_W1hi[HID * GK],   g_W1lo[HID * GK];
__device__ __nv_bfloat16  g_W2hi[HID * GK],   g_W2lo[HID * GK];
__device__ __nv_bfloat16  g_W3hi[OUT_F * GK], g_W3lo[OUT_F * GK];
__device__ float g_ns[N_NODES], g_nd[N_NODES];
__device__ int   g_deg_out[N_NODES], g_deg_in[N_NODES];
__device__ int   g_rowptr[N_NODES + 1], g_cursor[N_NODES], g_esrc[N_EDGES];
__device__ float g_proj[(size_t)N_SEL * N_DIM];

// ---------------- low-level helpers ------------------------------------------
__device__ __forceinline__ uint32_t smem_u32(const void* p) {
    uint32_t a;
    asm("{ .reg .u64 t; cvta.to.shared.u64 t, %1; cvt.u32.u64 %0, t; }" : "=r"(a) : "l"(p));
    return a;
}

__device__ __forceinline__ void ldm_x4(uint32_t* r, uint32_t addr) {
    asm volatile("ldmatrix.sync.aligned.m8n8.x4.shared.b16 {%0,%1,%2,%3}, [%4];"
        : "=r"(r[0]), "=r"(r[1]), "=r"(r[2]), "=r"(r[3]) : "r"(addr));
}

__device__ __forceinline__ void mma16816(float* c, const uint32_t* a, const uint32_t* b) {
    asm volatile("mma.sync.aligned.m16n8k16.row.col.f32.bf16.bf16.f32 "
        "{%0,%1,%2,%3}, {%4,%5,%6,%7}, {%8,%9}, {%0,%1,%2,%3};"
        : "+f"(c[0]), "+f"(c[1]), "+f"(c[2]), "+f"(c[3])
        : "r"(a[0]), "r"(a[1]), "r"(a[2]), "r"(a[3]), "r"(b[0]), "r"(b[1]));
}

// ---------------- graph preprocessing ----------------------------------------
__global__ void zero_deg_kernel() {
    int i = blockIdx.x * blockDim.x + threadIdx.x;
    for (; i < N_NODES; i += gridDim.x * blockDim.x) { g_deg_out[i] = 0; g_deg_in[i] = 0; }
}
__global__ void hist_kernel(const int* __restrict__ src, const int* __restrict__ dst) {
    int i = blockIdx.x * blockDim.x + threadIdx.x;
    for (; i < N_EDGES; i += gridDim.x * blockDim.x) {
        atomicAdd(&g_deg_out[src[i]], 1);
        atomicAdd(&g_deg_in[dst[i]], 1);
    }
}
__global__ void norm_kernel() {
    int i = blockIdx.x * blockDim.x + threadIdx.x;
    for (; i < N_NODES; i += gridDim.x * blockDim.x) {
        int dout = g_deg_out[i], din = g_deg_in[i];
        g_ns[i] = dout > 0 ? rsqrtf((float)dout) : 0.0f;
        g_nd[i] = din  > 0 ? rsqrtf((float)din)  : 0.0f;
    }
}
// chunked 2-pass scan: thread t owns elements [t*49, t*49+49)
__global__ void scan_kernel() {
    __shared__ int sh[1024];
    const int CH = 49;
    int t = threadIdx.x;
    int base = t * CH;
    int s = 0;
    for (int j = 0; j < CH; j++) { int i = base + j; if (i < N_NODES) s += g_deg_in[i]; }
    sh[t] = s;
    __syncthreads();
    #pragma unroll
    for (int off = 1; off < 1024; off <<= 1) {
        int v = (t >= off) ? sh[t - off] : 0;
        __syncthreads();
        sh[t] += v;
        __syncthreads();
    }
    int run = sh[t] - s;
    for (int j = 0; j < CH; j++) {
        int i = base + j;
        if (i < N_NODES) { g_rowptr[i] = run; g_cursor[i] = run; run += g_deg_in[i]; }
    }
    if (t == 1023) g_rowptr[N_NODES] = run;
}
__global__ void fill_kernel(const int* __restrict__ src, const int* __restrict__ dst) {
    int i = blockIdx.x * blockDim.x + threadIdx.x;
    for (; i < N_EDGES; i += gridDim.x * blockDim.x) {
        int p = atomicAdd(&g_cursor[dst[i]], 1);
        g_esrc[p] = src[i];
    }
}

// ---------------- hi/lo splitting ---------------------------------------------
__device__ __forceinline__ void split2(float a, float b, uint32_t& hi, uint32_t& lo) {
    __nv_bfloat16 ha = __float2bfloat16_rn(a);
    __nv_bfloat16 hb = __float2bfloat16_rn(b);
    __nv_bfloat16 la = __float2bfloat16_rn(a - __bfloat162float(ha));
    __nv_bfloat16 lb = __float2bfloat16_rn(b - __bfloat162float(hb));
    hi = (uint32_t)__bfloat16_as_ushort(ha) | ((uint32_t)__bfloat16_as_ushort(hb) << 16);
    lo = (uint32_t)__bfloat16_as_ushort(la) | ((uint32_t)__bfloat16_as_ushort(lb) << 16);
}

__global__ void conv_x_kernel(const float* __restrict__ x) {
    const float4* x4 = (const float4*)x;
    uint2* hi2 = (uint2*)g_Ahi;
    uint2* lo2 = (uint2*)g_Alo;
    size_t total = (size_t)N_NODES * IN_F / 4;
    for (size_t i = blockIdx.x * blockDim.x + threadIdx.x; i < total;
         i += (size_t)gridDim.x * blockDim.x) {
        float4 v = x4[i];
        uint2 h, l;
        split2(v.x, v.y, h.x, l.x);
        split2(v.z, v.w, h.y, l.y);
        hi2[i] = h;
        lo2[i] = l;
    }
}

// W [K, N] row-major -> W^T hi/lo stored [N, K]
__global__ void wprep_kernel(const float* __restrict__ W, __nv_bfloat16* __restrict__ Whi,
                             __nv_bfloat16* __restrict__ Wlo, int Kd, int Nd) {
    int total = Kd * Nd;
    for (int idx = blockIdx.x * blockDim.x + threadIdx.x; idx < total;
         idx += gridDim.x * blockDim.x) {
        int n = idx / Kd, k = idx - n * Kd;
        float v = W[(size_t)k * Nd + n];
        __nv_bfloat16 h = __float2bfloat16_rn(v);
        __nv_bfloat16 l = __float2bfloat16_rn(v - __bfloat162float(h));
        Whi[idx] = h;
        Wlo[idx] = l;
    }
}

// ---------------- tensor-core GEMM via mma.sync -------------------------------
// C[M,N] = (Ahi+Alo)[M,K] @ ((Whi+Wlo)[N,K])^T, 3-term bf16 split, fp32 acc.
// Block 128x128, BK=32, 8 warps of 64x32. SMEM rows padded to 40 bf16 (80 B).
#define SROW 80                       // bytes per smem row
#define TILE_BYTES (128 * SROW)       // 10240 B per matrix tile

__device__ __forceinline__ void load_tile32(const __nv_bfloat16* __restrict__ G, int row0,
                                            int rmax, char* s, int k0, int tid) {
    const uint4* g4 = (const uint4*)G;   // GK/8 = 64 uint4 per row
    #pragma unroll
    for (int i = 0; i < 2; i++) {
        int idx = tid + 256 * i;         // 0..511
        int r = idx >> 2, c = idx & 3;   // 128 rows x 4 uint4 (32 bf16)
        int gr = row0 + r;
        gr = gr < rmax ? gr : rmax - 1;
        uint4 v = g4[(size_t)gr * (GK / 8) + (k0 >> 3) + c];
        *(uint4*)(s + r * SROW + c * 16) = v;
    }
}

__global__ __launch_bounds__(256, 2)
void gemm_mma_kernel(const __nv_bfloat16* __restrict__ Ahi, const __nv_bfloat16* __restrict__ Alo,
                     const __nv_bfloat16* __restrict__ Whi, const __nv_bfloat16* __restrict__ Wlo,
                     float* __restrict__ C, int M, int N) {
    __shared__ __align__(16) char sm[4 * TILE_BYTES];
    char* sAH = sm;
    char* sAL = sm + TILE_BYTES;
    char* sWH = sm + 2 * TILE_BYTES;
    char* sWL = sm + 3 * TILE_BYTES;

    int tid = threadIdx.x;
    int wid = tid >> 5, lane = tid & 31;
    int tile_m = blockIdx.y * 128, tile_n = blockIdx.x * 128;
    int warp_m = (wid >> 2) * 64;      // 0 or 64
    int warp_n = (wid & 3) * 32;       // 0,32,64,96

    float acc[4][4][4];
    #pragma unroll
    for (int a = 0; a < 4; a++)
        #pragma unroll
        for (int b = 0; b < 4; b++)
            #pragma unroll
            for (int c = 0; c < 4; c++) acc[a][b][c] = 0.0f;

    uint32_t uAH = smem_u32(sAH), uAL = smem_u32(sAL);
    uint32_t uWH = smem_u32(sWH), uWL = smem_u32(sWL);

    // ldmatrix per-lane offsets (non-trans for both A[m][k] and W[n][k])
    int a_r  = lane & 15;               // row within 16
    int a_ko = (lane >> 4) << 3;        // k offset 0/8
    int b_g  = lane >> 3, b_i = lane & 7;
    int b_nr = ((b_g >> 1) << 3) + b_i; // n offset within 16
    int b_ko = (b_g & 1) << 3;          // k offset 0/8

    for (int ch = 0; ch < GK / 32; ch++) {
        int k0g = ch * 32;
        load_tile32(Ahi, tile_m, M, sAH, k0g, tid);
        load_tile32(Alo, tile_m, M, sAL, k0g, tid);
        load_tile32(Whi, tile_n, N, sWH, k0g, tid);
        load_tile32(Wlo, tile_n, N, sWL, k0g, tid);
        __syncthreads();

        #pragma unroll
        for (int ks = 0; ks < 2; ks++) {
            int k0 = ks * 16;
            uint32_t bh[2][4], bl[2][4], af[4][4];

            #pragma unroll
            for (int t = 0; t < 2; t++) {
                uint32_t noff = (uint32_t)(warp_n + t * 16 + b_nr) * SROW + (k0 + b_ko) * 2;
                ldm_x4(bh[t], uWH + noff);
                ldm_x4(bl[t], uWL + noff);
            }
            #pragma unroll
            for (int mt = 0; mt < 4; mt++) {
                uint32_t moff = (uint32_t)(warp_m + mt * 16 + a_r) * SROW + (k0 + a_ko) * 2;
                ldm_x4(af[mt], uAH + moff);
            }
            // term 1: Ahi x Whi, term 2: Ahi x Wlo
            #pragma unroll
            for (int mt = 0; mt < 4; mt++)
                #pragma unroll
                for (int nt = 0; nt < 4; nt++) {
                    mma16816(acc[mt][nt], af[mt], &bh[nt >> 1][(nt & 1) * 2]);
                    mma16816(acc[mt][nt], af[mt], &bl[nt >> 1][(nt & 1) * 2]);
                }
            // term 3: Alo x Whi (reuse af)
            #pragma unroll
            for (int mt = 0; mt < 4; mt++) {
                uint32_t moff = (uint32_t)(warp_m + mt * 16 + a_r) * SROW + (k0 + a_ko) * 2;
                ldm_x4(af[mt], uAL + moff);
            }
            #pragma unroll
            for (int mt = 0; mt < 4; mt++)
                #pragma unroll
                for (int nt = 0; nt < 4; nt++)
                    mma16816(acc[mt][nt], af[mt], &bh[nt >> 1][(nt & 1) * 2]);
        }
        __syncthreads();
    }

    // epilogue: c0,c1 -> (row=lane/4, col=(lane%4)*2), c2,c3 -> row+8
    int er = lane >> 2, ec = (lane & 3) << 1;
    #pragma unroll
    for (int mt = 0; mt < 4; mt++) {
        #pragma unroll
        for (int nt = 0; nt < 4; nt++) {
            int r0 = tile_m + warp_m + mt * 16 + er;
            int c0 = tile_n + warp_n + nt * 8 + ec;
            if (r0 < M)
                *(float2*)&C[(size_t)r0 * N + c0] = make_float2(acc[mt][nt][0], acc[mt][nt][1]);
            if (r0 + 8 < M)
                *(float2*)&C[(size_t)(r0 + 8) * N + c0] = make_float2(acc[mt][nt][2], acc[mt][nt][3]);
        }
    }
}

// ---------------- CSR aggregation; optional bf16 hi/lo epilogue ----------------
__global__ void agg_kernel(const float* __restrict__ Z, const float* __restrict__ bias,
                           float* __restrict__ outF,
                           __nv_bfloat16* __restrict__ outHi, __nv_bfloat16* __restrict__ outLo,
                           int F, int bf16_out) {
    int d = blockIdx.x;
    int t = threadIdx.x;          // blockDim = F/4
    int nvec = F >> 2;

    float4 acc = make_float4(0.f, 0.f, 0.f, 0.f);
    int beg = g_rowptr[d], end = g_rowptr[d + 1];
    const float4* Z4 = (const float4*)Z;
    for (int e = beg; e < end; ++e) {
        int s = g_esrc[e];
        float w = g_ns[s];
        float4 z = Z4[(size_t)s * nvec + t];
        acc.x = fmaf(w, z.x, acc.x);
        acc.y = fmaf(w, z.y, acc.y);
        acc.z = fmaf(w, z.z, acc.z);
        acc.w = fmaf(w, z.w, acc.w);
    }
    float ndv = g_nd[d];
    float4 b = ((const float4*)bias)[t];
    float4 r;
    r.x = fmaxf(fmaf(ndv, acc.x, b.x), 0.f);
    r.y = fmaxf(fmaf(ndv, acc.y, b.y), 0.f);
    r.z = fmaxf(fmaf(ndv, acc.z, b.z), 0.f);
    r.w = fmaxf(fmaf(ndv, acc.w, b.w), 0.f);
    if (bf16_out) {
        uint2 h, l;
        split2(r.x, r.y, h.x, l.x);
        split2(r.z, r.w, h.y, l.y);
        ((uint2*)outHi)[(size_t)d * nvec + t] = h;
        ((uint2*)outLo)[(size_t)d * nvec + t] = l;
    } else {
        ((float4*)outF)[(size_t)d * nvec + t] = r;
    }
}

// ---------------- proj = h3[x_indices] @ Wp + bp -------------------------------
__global__ __launch_bounds__(128)
void proj_kernel(const float* __restrict__ H, const int* __restrict__ xidx,
                 const float* __restrict__ Wp, const float* __restrict__ bp,
                 float* __restrict__ P) {
    __shared__ float enc[OUT_F];
    int m = blockIdx.x;
    int t = threadIdx.x;
    int row = xidx[m];
    enc[t]       = H[(size_t)row * OUT_F + t];
    enc[t + 128] = H[(size_t)row * OUT_F + t + 128];
    __syncthreads();
    float a0 = 0.f, a1 = 0.f, a2 = 0.f, a3 = 0.f;
    #pragma unroll 4
    for (int k = 0; k < OUT_F; k += 4) {
        a0 = fmaf(enc[k + 0], Wp[(size_t)(k + 0) * N_DIM + t], a0);
        a1 = fmaf(enc[k + 1], Wp[(size_t)(k + 1) * N_DIM + t], a1);
        a2 = fmaf(enc[k + 2], Wp[(size_t)(k + 2) * N_DIM + t], a2);
        a3 = fmaf(enc[k + 3], Wp[(size_t)(k + 3) * N_DIM + t], a3);
    }
    P[(size_t)m * N_DIM + t] = bp[t] + (a0 + a1) + (a2 + a3);
}

// ---------------- out[c][s] = dot(emb[c_indices[c]], proj[s]) ------------------
__global__ __launch_bounds__(256)
void out_gemm_kernel(const float* __restrict__ emb, const int* __restrict__ cidx,
                     const float* __restrict__ P, float* __restrict__ out) {
    __shared__ float Es[64][33];
    __shared__ float Ps[64][33];
    int s0 = blockIdx.x * 64;
    int c0 = blockIdx.y * 64;
    int tid = threadIdx.x;
    int tx = tid & 15, ty = tid >> 4;

    float acc[4][4];
    #pragma unroll
    for (int i = 0; i < 4; i++)
        #pragma unroll
        for (int j = 0; j < 4; j++) acc[i][j] = 0.f;

    for (int k0 = 0; k0 < N_DIM; k0 += 32) {
        #pragma unroll
        for (int i = 0; i < 2; i++) {
            int idx = tid * 2 + i;
            int r = idx >> 3;
            int c = (idx & 7) * 4;
            int erow = cidx[c0 + r];
            float4 v = *(const float4*)&emb[(size_t)erow * N_DIM + k0 + c];
            Es[r][c] = v.x; Es[r][c + 1] = v.y; Es[r][c + 2] = v.z; Es[r][c + 3] = v.w;
            float4 p = *(const float4*)&P[(size_t)(s0 + r) * N_DIM + k0 + c];
            Ps[r][c] = p.x; Ps[r][c + 1] = p.y; Ps[r][c + 2] = p.z; Ps[r][c + 3] = p.w;
        }
        __syncthreads();
        #pragma unroll
        for (int kk = 0; kk < 32; kk++) {
            float a[4], b[4];
            #pragma unroll
            for (int i = 0; i < 4; i++) a[i] = Es[ty * 4 + i][kk];
            #pragma unroll
            for (int j = 0; j < 4; j++) b[j] = Ps[tx * 4 + j][kk];
            #pragma unroll
            for (int i = 0; i < 4; i++)
                #pragma unroll
                for (int j = 0; j < 4; j++) acc[i][j] = fmaf(a[i], b[j], acc[i][j]);
        }
        __syncthreads();
    }
    #pragma unroll
    for (int i = 0; i < 4; i++) {
        float4 v = make_float4(acc[i][0], acc[i][1], acc[i][2], acc[i][3]);
        *(float4*)&out[(size_t)(c0 + ty * 4 + i) * N_SEL + s0 + tx * 4] = v;
    }
}

// ---------------- launch --------------------------------------------------------
extern "C" void kernel_launch(void* const* d_in, const int* in_sizes, int n_in,
                              void* d_out, int out_size) {
    const float* x    = (const float*)d_in[0];
    const int*   src  = (const int*)d_in[1];
    const int*   dst  = (const int*)d_in[2];
    const int*   xidx = (const int*)d_in[3];
    const int*   cidx = (const int*)d_in[4];
    const float* W1   = (const float*)d_in[5];
    const float* b1   = (const float*)d_in[6];
    const float* W2   = (const float*)d_in[7];
    const float* b2   = (const float*)d_in[8];
    const float* W3   = (const float*)d_in[9];
    const float* b3   = (const float*)d_in[10];
    const float* Wp   = (const float*)d_in[11];
    const float* bp   = (const float*)d_in[12];
    const float* emb  = (const float*)d_in[13];
    float* out = (float*)d_out;

    float *Zb, *h3b, *projb;
    __nv_bfloat16 *Ahi, *Alo, *W1hi, *W1lo, *W2hi, *W2lo, *W3hi, *W3lo;
    cudaGetSymbolAddress((void**)&Zb, g_Z);
    cudaGetSymbolAddress((void**)&h3b, g_h3);
    cudaGetSymbolAddress((void**)&projb, g_proj);
    cudaGetSymbolAddress((void**)&Ahi, g_Ahi);
    cudaGetSymbolAddress((void**)&Alo, g_Alo);
    cudaGetSymbolAddress((void**)&W1hi, g_W1hi);
    cudaGetSymbolAddress((void**)&W1lo, g_W1lo);
    cudaGetSymbolAddress((void**)&W2hi, g_W2hi);
    cudaGetSymbolAddress((void**)&W2lo, g_W2lo);
    cudaGetSymbolAddress((void**)&W3hi, g_W3hi);
    cudaGetSymbolAddress((void**)&W3lo, g_W3lo);

    // graph preprocessing
    zero_deg_kernel<<<196, 256>>>();
    hist_kernel<<<512, 256>>>(src, dst);
    norm_kernel<<<196, 256>>>();
    scan_kernel<<<1, 1024>>>();
    fill_kernel<<<512, 256>>>(src, dst);

    // data prep: split x and weights into bf16 hi/lo (weights transposed to [N,K])
    conv_x_kernel<<<512, 256>>>(x);
    wprep_kernel<<<256, 256>>>(W1, W1hi, W1lo, GK, HID);
    wprep_kernel<<<256, 256>>>(W2, W2hi, W2lo, GK, HID);
    wprep_kernel<<<128, 256>>>(W3, W3hi, W3lo, GK, OUT_F);

    const int MB = (N_NODES + 127) / 128;   // 391

    // Layer 1
    gemm_mma_kernel<<<dim3(HID / 128, MB), 256>>>(Ahi, Alo, W1hi, W1lo, Zb, N_NODES, HID);
    agg_kernel<<<N_NODES, HID / 4>>>(Zb, b1, nullptr, Ahi, Alo, HID, 1);

    // Layer 2
    gemm_mma_kernel<<<dim3(HID / 128, MB), 256>>>(Ahi, Alo, W2hi, W2lo, Zb, N_NODES, HID);
    agg_kernel<<<N_NODES, HID / 4>>>(Zb, b2, nullptr, Ahi, Alo, HID, 1);

    // Layer 3 (N = 256), agg -> fp32 h3
    gemm_mma_kernel<<<dim3(OUT_F / 128, MB), 256>>>(Ahi, Alo, W3hi, W3lo, Zb, N_NODES, OUT_F);
    agg_kernel<<<N_NODES, OUT_F / 4>>>(Zb, b3, h3b, nullptr, nullptr, OUT_F, 0);

    // proj = h3[x_indices] @ Wp + bp
    proj_kernel<<<N_SEL, 128>>>(h3b, xidx, Wp, bp, projb);

    // out = emb[c_indices] @ proj.T
    out_gemm_kernel<<<dim3(N_SEL / 64, N_C / 64), 256>>>(emb, cidx, projb, out);
}

// round 4
// speedup vs baseline: 2.2220x; 1.1294x over previous
#include <cuda_runtime.h>
#include <cuda_bf16.h>
#include <math.h>
#include <stdint.h>

#define N_NODES 50000
#define N_EDGES 400000
#define IN_F    512
#define HID     512
#define OUT_F   256
#define N_SEL   8192
#define N_C     1024
#define N_DIM   128
#define GK      512        // K of all three big GEMMs

// ---------------- scratch (device globals) ----------------------------------
__device__ float          g_Z  [(size_t)N_NODES * HID];     // GEMM output (pre-agg)
__device__ float          g_h3 [(size_t)N_NODES * OUT_F];   // layer-3 activations
__device__ __nv_bfloat16  g_Ahi[(size_t)N_NODES * HID];
__device__ __nv_bfloat16  g_Alo[(size_t)N_NODES * HID];
__device__ __nv_bfloat16  g_W1hi[HID * GK],   g_W1lo[HID * GK];
__device__ __nv_bfloat16  g_W2hi[HID * GK],   g_W2lo[HID * GK];
__device__ __nv_bfloat16  g_W3hi[OUT_F * GK], g_W3lo[OUT_F * GK];
__device__ float g_ns[N_NODES], g_nd[N_NODES];
__device__ int   g_deg_out[N_NODES], g_deg_in[N_NODES];
__device__ int   g_rowptr[N_NODES + 1], g_cursor[N_NODES], g_esrc[N_EDGES];
__device__ int   g_blockSums[256];
__device__ float g_proj[(size_t)N_SEL * N_DIM];

#define SCAN_BLOCKS 196   // 196*256 = 50176 >= N_NODES

// ---------------- low-level helpers ------------------------------------------
__device__ __forceinline__ uint32_t smem_u32(const void* p) {
    uint32_t a;
    asm("{ .reg .u64 t; cvta.to.shared.u64 t, %1; cvt.u32.u64 %0, t; }" : "=r"(a) : "l"(p));
    return a;
}
__device__ __forceinline__ void ldm_x4(uint32_t* r, uint32_t addr) {
    asm volatile("ldmatrix.sync.aligned.m8n8.x4.shared.b16 {%0,%1,%2,%3}, [%4];"
        : "=r"(r[0]), "=r"(r[1]), "=r"(r[2]), "=r"(r[3]) : "r"(addr));
}
__device__ __forceinline__ void mma16816(float* c, const uint32_t* a, const uint32_t* b) {
    asm volatile("mma.sync.aligned.m16n8k16.row.col.f32.bf16.bf16.f32 "
        "{%0,%1,%2,%3}, {%4,%5,%6,%7}, {%8,%9}, {%0,%1,%2,%3};"
        : "+f"(c[0]), "+f"(c[1]), "+f"(c[2]), "+f"(c[3])
        : "r"(a[0]), "r"(a[1]), "r"(a[2]), "r"(a[3]), "r"(b[0]), "r"(b[1]));
}
__device__ __forceinline__ void cp16(uint32_t saddr, const void* g) {
    asm volatile("cp.async.cg.shared.global [%0], [%1], 16;" :: "r"(saddr), "l"(g));
}
#define CP_COMMIT() asm volatile("cp.async.commit_group;" ::: "memory")
#define CP_WAIT(n)  asm volatile("cp.async.wait_group %0;" :: "n"(n) : "memory")

// ---------------- graph preprocessing ----------------------------------------
__global__ void zero_deg_kernel() {
    int i = blockIdx.x * blockDim.x + threadIdx.x;
    for (; i < N_NODES; i += gridDim.x * blockDim.x) { g_deg_out[i] = 0; g_deg_in[i] = 0; }
}
__global__ void hist_kernel(const int* __restrict__ src, const int* __restrict__ dst) {
    int i = blockIdx.x * blockDim.x + threadIdx.x;
    for (; i < N_EDGES; i += gridDim.x * blockDim.x) {
        atomicAdd(&g_deg_out[src[i]], 1);
        atomicAdd(&g_deg_in[dst[i]], 1);
    }
}
__global__ void norm_kernel() {
    int i = blockIdx.x * blockDim.x + threadIdx.x;
    for (; i < N_NODES; i += gridDim.x * blockDim.x) {
        int dout = g_deg_out[i], din = g_deg_in[i];
        g_ns[i] = dout > 0 ? rsqrtf((float)dout) : 0.0f;
        g_nd[i] = din  > 0 ? rsqrtf((float)din)  : 0.0f;
    }
}

// parallel 3-phase scan of g_deg_in -> g_rowptr/g_cursor
__global__ void scan1_kernel() {
    __shared__ int sh[256];
    int b = blockIdx.x, t = threadIdx.x;
    int i = b * 256 + t;
    sh[t] = (i < N_NODES) ? g_deg_in[i] : 0;
    __syncthreads();
    #pragma unroll
    for (int off = 128; off > 0; off >>= 1) {
        if (t < off) sh[t] += sh[t + off];
        __syncthreads();
    }
    if (t == 0) g_blockSums[b] = sh[0];
}
__global__ void scan2_kernel() {
    __shared__ int sh[256];
    int t = threadIdx.x;
    int v = (t < SCAN_BLOCKS) ? g_blockSums[t] : 0;
    sh[t] = v;
    __syncthreads();
    #pragma unroll
    for (int off = 1; off < 256; off <<= 1) {
        int x = (t >= off) ? sh[t - off] : 0;
        __syncthreads();
        sh[t] += x;
        __syncthreads();
    }
    if (t < SCAN_BLOCKS) g_blockSums[t] = sh[t] - v;   // exclusive block offsets
    if (t == 255) g_rowptr[N_NODES] = sh[255];
}
__global__ void scan3_kernel() {
    __shared__ int sh[256];
    int b = blockIdx.x, t = threadIdx.x;
    int i = b * 256 + t;
    int v = (i < N_NODES) ? g_deg_in[i] : 0;
    sh[t] = v;
    __syncthreads();
    #pragma unroll
    for (int off = 1; off < 256; off <<= 1) {
        int x = (t >= off) ? sh[t - off] : 0;
        __syncthreads();
        sh[t] += x;
        __syncthreads();
    }
    if (i < N_NODES) {
        int excl = g_blockSums[b] + sh[t] - v;
        g_rowptr[i] = excl;
        g_cursor[i] = excl;
    }
}
__global__ void fill_kernel(const int* __restrict__ src, const int* __restrict__ dst) {
    int i = blockIdx.x * blockDim.x + threadIdx.x;
    for (; i < N_EDGES; i += gridDim.x * blockDim.x) {
        int p = atomicAdd(&g_cursor[dst[i]], 1);
        g_esrc[p] = src[i];
    }
}

// ---------------- hi/lo splitting ---------------------------------------------
__device__ __forceinline__ void split2(float a, float b, uint32_t& hi, uint32_t& lo) {
    __nv_bfloat16 ha = __float2bfloat16_rn(a);
    __nv_bfloat16 hb = __float2bfloat16_rn(b);
    __nv_bfloat16 la = __float2bfloat16_rn(a - __bfloat162float(ha));
    __nv_bfloat16 lb = __float2bfloat16_rn(b - __bfloat162float(hb));
    hi = (uint32_t)__bfloat16_as_ushort(ha) | ((uint32_t)__bfloat16_as_ushort(hb) << 16);
    lo = (uint32_t)__bfloat16_as_ushort(la) | ((uint32_t)__bfloat16_as_ushort(lb) << 16);
}

__global__ void conv_x_kernel(const float* __restrict__ x) {
    const float4* x4 = (const float4*)x;
    uint2* hi2 = (uint2*)g_Ahi;
    uint2* lo2 = (uint2*)g_Alo;
    size_t total = (size_t)N_NODES * IN_F / 4;
    for (size_t i = blockIdx.x * blockDim.x + threadIdx.x; i < total;
         i += (size_t)gridDim.x * blockDim.x) {
        float4 v = x4[i];
        uint2 h, l;
        split2(v.x, v.y, h.x, l.x);
        split2(v.z, v.w, h.y, l.y);
        hi2[i] = h;
        lo2[i] = l;
    }
}

// W [K, N] row-major -> W^T hi/lo stored [N, K]
__global__ void wprep_kernel(const float* __restrict__ W, __nv_bfloat16* __restrict__ Whi,
                             __nv_bfloat16* __restrict__ Wlo, int Kd, int Nd) {
    int total = Kd * Nd;
    for (int idx = blockIdx.x * blockDim.x + threadIdx.x; idx < total;
         idx += gridDim.x * blockDim.x) {
        int n = idx / Kd, k = idx - n * Kd;
        float v = W[(size_t)k * Nd + n];
        __nv_bfloat16 h = __float2bfloat16_rn(v);
        __nv_bfloat16 l = __float2bfloat16_rn(v - __bfloat162float(h));
        Whi[idx] = h;
        Wlo[idx] = l;
    }
}

// ---------------- tensor-core GEMM via mma.sync + cp.async pipeline -----------
// C[M,N] = (Ahi+Alo)[M,K] @ ((Whi+Wlo)[N,K])^T, 3-term bf16 split, fp32 acc.
// Block 128x128, BK=32, 8 warps of 64x32, 2-stage cp.async double buffering.
#define SROW 80                        // bytes per smem row (40 bf16)
#define TILE_BYTES (128 * SROW)        // 10240 B
#define STAGE_BYTES (4 * TILE_BYTES)   // 40960 B
#define GEMM_SMEM (2 * STAGE_BYTES)    // 81920 B dynamic

__device__ __forceinline__ void issue_tile32(const __nv_bfloat16* __restrict__ G, int row0,
                                             int rmax, uint32_t sbase, int k0, int tid) {
    const char* g = (const char*)G;
    #pragma unroll
    for (int i = 0; i < 2; i++) {
        int idx = tid + 256 * i;          // 0..511
        int r = idx >> 2, c = idx & 3;    // 128 rows x 4 x 16B
        int gr = row0 + r;
        gr = gr < rmax ? gr : rmax - 1;
        cp16(sbase + r * SROW + c * 16,
             g + (size_t)gr * (GK * 2) + (size_t)k0 * 2 + c * 16);
    }
}

__global__ __launch_bounds__(256, 2)
void gemm_mma_kernel(const __nv_bfloat16* __restrict__ Ahi, const __nv_bfloat16* __restrict__ Alo,
                     const __nv_bfloat16* __restrict__ Whi, const __nv_bfloat16* __restrict__ Wlo,
                     float* __restrict__ C, int M, int N) {
    extern __shared__ __align__(16) char sm[];
    uint32_t u0 = smem_u32(sm);

    int tid = threadIdx.x;
    int wid = tid >> 5, lane = tid & 31;
    int tile_m = blockIdx.y * 128, tile_n = blockIdx.x * 128;
    int warp_m = (wid >> 2) * 64;      // 0 or 64
    int warp_n = (wid & 3) * 32;       // 0,32,64,96

    float acc[4][4][4];
    #pragma unroll
    for (int a = 0; a < 4; a++)
        #pragma unroll
        for (int b = 0; b < 4; b++)
            #pragma unroll
            for (int c = 0; c < 4; c++) acc[a][b][c] = 0.0f;

    // ldmatrix per-lane offsets
    int a_r  = lane & 15;
    int a_ko = (lane >> 4) << 3;
    int b_g  = lane >> 3, b_i = lane & 7;
    int b_nr = ((b_g >> 1) << 3) + b_i;
    int b_ko = (b_g & 1) << 3;

    const int NCH = GK / 32;   // 16

    // prefetch chunk 0 into stage 0
    {
        uint32_t st = u0;
        issue_tile32(Ahi, tile_m, M, st,                  0, tid);
        issue_tile32(Alo, tile_m, M, st + TILE_BYTES,     0, tid);
        issue_tile32(Whi, tile_n, N, st + 2 * TILE_BYTES, 0, tid);
        issue_tile32(Wlo, tile_n, N, st + 3 * TILE_BYTES, 0, tid);
        CP_COMMIT();
    }

    for (int ch = 0; ch < NCH; ch++) {
        if (ch + 1 < NCH) {
            uint32_t st = u0 + ((ch + 1) & 1) * STAGE_BYTES;
            int k0g = (ch + 1) * 32;
            issue_tile32(Ahi, tile_m, M, st,                  k0g, tid);
            issue_tile32(Alo, tile_m, M, st + TILE_BYTES,     k0g, tid);
            issue_tile32(Whi, tile_n, N, st + 2 * TILE_BYTES, k0g, tid);
            issue_tile32(Wlo, tile_n, N, st + 3 * TILE_BYTES, k0g, tid);
            CP_COMMIT();
            CP_WAIT(1);
        } else {
            CP_WAIT(0);
        }
        __syncthreads();

        uint32_t stc = u0 + (ch & 1) * STAGE_BYTES;
        uint32_t uAH = stc, uAL = stc + TILE_BYTES;
        uint32_t uWH = stc + 2 * TILE_BYTES, uWL = stc + 3 * TILE_BYTES;

        #pragma unroll
        for (int ks = 0; ks < 2; ks++) {
            int k0 = ks * 16;
            uint32_t bh[2][4], bl[2][4], af[4][4];
            #pragma unroll
            for (int t = 0; t < 2; t++) {
                uint32_t noff = (uint32_t)(warp_n + t * 16 + b_nr) * SROW + (k0 + b_ko) * 2;
                ldm_x4(bh[t], uWH + noff);
                ldm_x4(bl[t], uWL + noff);
            }
            #pragma unroll
            for (int mt = 0; mt < 4; mt++) {
                uint32_t moff = (uint32_t)(warp_m + mt * 16 + a_r) * SROW + (k0 + a_ko) * 2;
                ldm_x4(af[mt], uAH + moff);
            }
            #pragma unroll
            for (int mt = 0; mt < 4; mt++)
                #pragma unroll
                for (int nt = 0; nt < 4; nt++) {
                    mma16816(acc[mt][nt], af[mt], &bh[nt >> 1][(nt & 1) * 2]);
                    mma16816(acc[mt][nt], af[mt], &bl[nt >> 1][(nt & 1) * 2]);
                }
            #pragma unroll
            for (int mt = 0; mt < 4; mt++) {
                uint32_t moff = (uint32_t)(warp_m + mt * 16 + a_r) * SROW + (k0 + a_ko) * 2;
                ldm_x4(af[mt], uAL + moff);
            }
            #pragma unroll
            for (int mt = 0; mt < 4; mt++)
                #pragma unroll
                for (int nt = 0; nt < 4; nt++)
                    mma16816(acc[mt][nt], af[mt], &bh[nt >> 1][(nt & 1) * 2]);
        }
        __syncthreads();
    }

    int er = lane >> 2, ec = (lane & 3) << 1;
    #pragma unroll
    for (int mt = 0; mt < 4; mt++) {
        #pragma unroll
        for (int nt = 0; nt < 4; nt++) {
            int r0 = tile_m + warp_m + mt * 16 + er;
            int c0 = tile_n + warp_n + nt * 8 + ec;
            if (r0 < M)
                *(float2*)&C[(size_t)r0 * N + c0] = make_float2(acc[mt][nt][0], acc[mt][nt][1]);
            if (r0 + 8 < M)
                *(float2*)&C[(size_t)(r0 + 8) * N + c0] = make_float2(acc[mt][nt][2], acc[mt][nt][3]);
        }
    }
}

// ---------------- CSR aggregation; optional bf16 hi/lo epilogue ----------------
__global__ void agg_kernel(const float* __restrict__ Z, const float* __restrict__ bias,
                           float* __restrict__ outF,
                           __nv_bfloat16* __restrict__ outHi, __nv_bfloat16* __restrict__ outLo,
                           int F, int bf16_out) {
    int d = blockIdx.x;
    int t = threadIdx.x;          // blockDim = F/4
    int nvec = F >> 2;

    float4 acc = make_float4(0.f, 0.f, 0.f, 0.f);
    int beg = g_rowptr[d], end = g_rowptr[d + 1];
    const float4* Z4 = (const float4*)Z;
    for (int e = beg; e < end; ++e) {
        int s = g_esrc[e];
        float w = g_ns[s];
        float4 z = Z4[(size_t)s * nvec + t];
        acc.x = fmaf(w, z.x, acc.x);
        acc.y = fmaf(w, z.y, acc.y);
        acc.z = fmaf(w, z.z, acc.z);
        acc.w = fmaf(w, z.w, acc.w);
    }
    float ndv = g_nd[d];
    float4 b = ((const float4*)bias)[t];
    float4 r;
    r.x = fmaxf(fmaf(ndv, acc.x, b.x), 0.f);
    r.y = fmaxf(fmaf(ndv, acc.y, b.y), 0.f);
    r.z = fmaxf(fmaf(ndv, acc.z, b.z), 0.f);
    r.w = fmaxf(fmaf(ndv, acc.w, b.w), 0.f);
    if (bf16_out) {
        uint2 h, l;
        split2(r.x, r.y, h.x, l.x);
        split2(r.z, r.w, h.y, l.y);
        ((uint2*)outHi)[(size_t)d * nvec + t] = h;
        ((uint2*)outLo)[(size_t)d * nvec + t] = l;
    } else {
        ((float4*)outF)[(size_t)d * nvec + t] = r;
    }
}

// ---------------- proj = h3[x_indices] @ Wp + bp -------------------------------
__global__ __launch_bounds__(128)
void proj_kernel(const float* __restrict__ H, const int* __restrict__ xidx,
                 const float* __restrict__ Wp, const float* __restrict__ bp,
                 float* __restrict__ P) {
    __shared__ float enc[OUT_F];
    int m = blockIdx.x;
    int t = threadIdx.x;
    int row = xidx[m];
    enc[t]       = H[(size_t)row * OUT_F + t];
    enc[t + 128] = H[(size_t)row * OUT_F + t + 128];
    __syncthreads();
    float a0 = 0.f, a1 = 0.f, a2 = 0.f, a3 = 0.f;
    #pragma unroll 4
    for (int k = 0; k < OUT_F; k += 4) {
        a0 = fmaf(enc[k + 0], Wp[(size_t)(k + 0) * N_DIM + t], a0);
        a1 = fmaf(enc[k + 1], Wp[(size_t)(k + 1) * N_DIM + t], a1);
        a2 = fmaf(enc[k + 2], Wp[(size_t)(k + 2) * N_DIM + t], a2);
        a3 = fmaf(enc[k + 3], Wp[(size_t)(k + 3) * N_DIM + t], a3);
    }
    P[(size_t)m * N_DIM + t] = bp[t] + (a0 + a1) + (a2 + a3);
}

// ---------------- out[c][s] = dot(emb[c_indices[c]], proj[s]) ------------------
__global__ __launch_bounds__(256)
void out_gemm_kernel(const float* __restrict__ emb, const int* __restrict__ cidx,
                     const float* __restrict__ P, float* __restrict__ out) {
    __shared__ float Es[64][33];
    __shared__ float Ps[64][33];
    int s0 = blockIdx.x * 64;
    int c0 = blockIdx.y * 64;
    int tid = threadIdx.x;
    int tx = tid & 15, ty = tid >> 4;

    float acc[4][4];
    #pragma unroll
    for (int i = 0; i < 4; i++)
        #pragma unroll
        for (int j = 0; j < 4; j++) acc[i][j] = 0.f;

    for (int k0 = 0; k0 < N_DIM; k0 += 32) {
        #pragma unroll
        for (int i = 0; i < 2; i++) {
            int idx = tid * 2 + i;
            int r = idx >> 3;
            int c = (idx & 7) * 4;
            int erow = cidx[c0 + r];
            float4 v = *(const float4*)&emb[(size_t)erow * N_DIM + k0 + c];
            Es[r][c] = v.x; Es[r][c + 1] = v.y; Es[r][c + 2] = v.z; Es[r][c + 3] = v.w;
            float4 p = *(const float4*)&P[(size_t)(s0 + r) * N_DIM + k0 + c];
            Ps[r][c] = p.x; Ps[r][c + 1] = p.y; Ps[r][c + 2] = p.z; Ps[r][c + 3] = p.w;
        }
        __syncthreads();
        #pragma unroll
        for (int kk = 0; kk < 32; kk++) {
            float a[4], b[4];
            #pragma unroll
            for (int i = 0; i < 4; i++) a[i] = Es[ty * 4 + i][kk];
            #pragma unroll
            for (int j = 0; j < 4; j++) b[j] = Ps[tx * 4 + j][kk];
            #pragma unroll
            for (int i = 0; i < 4; i++)
                #pragma unroll
                for (int j = 0; j < 4; j++) acc[i][j] = fmaf(a[i], b[j], acc[i][j]);
        }
        __syncthreads();
    }
    #pragma unroll
    for (int i = 0; i < 4; i++) {
        float4 v = make_float4(acc[i][0], acc[i][1], acc[i][2], acc[i][3]);
        *(float4*)&out[(size_t)(c0 + ty * 4 + i) * N_SEL + s0 + tx * 4] = v;
    }
}

// ---------------- launch --------------------------------------------------------
extern "C" void kernel_launch(void* const* d_in, const int* in_sizes, int n_in,
                              void* d_out, int out_size) {
    const float* x    = (const float*)d_in[0];
    const int*   src  = (const int*)d_in[1];
    const int*   dst  = (const int*)d_in[2];
    const int*   xidx = (const int*)d_in[3];
    const int*   cidx = (const int*)d_in[4];
    const float* W1   = (const float*)d_in[5];
    const float* b1   = (const float*)d_in[6];
    const float* W2   = (const float*)d_in[7];
    const float* b2   = (const float*)d_in[8];
    const float* W3   = (const float*)d_in[9];
    const float* b3   = (const float*)d_in[10];
    const float* Wp   = (const float*)d_in[11];
    const float* bp   = (const float*)d_in[12];
    const float* emb  = (const float*)d_in[13];
    float* out = (float*)d_out;

    static int smem_set = 0;
    if (!smem_set) {
        cudaFuncSetAttribute(gemm_mma_kernel, cudaFuncAttributeMaxDynamicSharedMemorySize,
                             GEMM_SMEM);
        smem_set = 1;
    }

    float *Zb, *h3b, *projb;
    __nv_bfloat16 *Ahi, *Alo, *W1hi, *W1lo, *W2hi, *W2lo, *W3hi, *W3lo;
    cudaGetSymbolAddress((void**)&Zb, g_Z);
    cudaGetSymbolAddress((void**)&h3b, g_h3);
    cudaGetSymbolAddress((void**)&projb, g_proj);
    cudaGetSymbolAddress((void**)&Ahi, g_Ahi);
    cudaGetSymbolAddress((void**)&Alo, g_Alo);
    cudaGetSymbolAddress((void**)&W1hi, g_W1hi);
    cudaGetSymbolAddress((void**)&W1lo, g_W1lo);
    cudaGetSymbolAddress((void**)&W2hi, g_W2hi);
    cudaGetSymbolAddress((void**)&W2lo, g_W2lo);
    cudaGetSymbolAddress((void**)&W3hi, g_W3hi);
    cudaGetSymbolAddress((void**)&W3lo, g_W3lo);

    // graph preprocessing
    zero_deg_kernel<<<196, 256>>>();
    hist_kernel<<<512, 256>>>(src, dst);
    norm_kernel<<<196, 256>>>();
    scan1_kernel<<<SCAN_BLOCKS, 256>>>();
    scan2_kernel<<<1, 256>>>();
    scan3_kernel<<<SCAN_BLOCKS, 256>>>();
    fill_kernel<<<512, 256>>>(src, dst);

    // data prep: split x and weights into bf16 hi/lo (weights transposed to [N,K])
    conv_x_kernel<<<512, 256>>>(x);
    wprep_kernel<<<256, 256>>>(W1, W1hi, W1lo, GK, HID);
    wprep_kernel<<<256, 256>>>(W2, W2hi, W2lo, GK, HID);
    wprep_kernel<<<128, 256>>>(W3, W3hi, W3lo, GK, OUT_F);

    const int MB = (N_NODES + 127) / 128;   // 391

    // Layer 1
    gemm_mma_kernel<<<dim3(HID / 128, MB), 256, GEMM_SMEM>>>(Ahi, Alo, W1hi, W1lo, Zb, N_NODES, HID);
    agg_kernel<<<N_NODES, HID / 4>>>(Zb, b1, nullptr, Ahi, Alo, HID, 1);

    // Layer 2
    gemm_mma_kernel<<<dim3(HID / 128, MB), 256, GEMM_SMEM>>>(Ahi, Alo, W2hi, W2lo, Zb, N_NODES, HID);
    agg_kernel<<<N_NODES, HID / 4>>>(Zb, b2, nullptr, Ahi, Alo, HID, 1);

    // Layer 3 (N = 256), agg -> fp32 h3
    gemm_mma_kernel<<<dim3(OUT_F / 128, MB), 256, GEMM_SMEM>>>(Ahi, Alo, W3hi, W3lo, Zb, N_NODES, OUT_F);
    agg_kernel<<<N_NODES, OUT_F / 4>>>(Zb, b3, h3b, nullptr, nullptr, OUT_F, 0);

    // proj = h3[x_indices] @ Wp + bp
    proj_kernel<<<N_SEL, 128>>>(h3b, xidx, Wp, bp, projb);

    // out = emb[c_indices] @ proj.T
    out_gemm_kernel<<<dim3(N_SEL / 64, N_C / 64), 256>>>(emb, cidx, projb, out);
}